// round 10
// baseline (speedup 1.0000x reference)
#include <cuda_runtime.h>
#include <cuda_fp16.h>
#include <cstdint>
#include <math.h>

// Shapes fixed by the reference: B=32, N=4096, D=256, H=256
#define BB 32
#define NN 4096
#define DD 256
#define HH 256
#define MTOT (BB * NN)          // 131072 rows
#define TILE_M 32               // rows per CTA
#define NTILES (MTOT / TILE_M)  // 4096
#define NCHUNK 128
#define KC 32                   // d-chunk
#define SA 40                   // padded smem row stride in fp16 elems (80 B)
#define A_BYTES (TILE_M * SA * 2)     // 2560
#define B_BYTES (HH * SA * 2)         // 20480
#define BUF_BYTES (A_BYTES + B_BYTES) // 23040
#define DYN_SMEM (2 * BUF_BYTES)      // 46080

// ---------------- device scratch (no allocation allowed) ----------------
__device__ float g_scores[MTOT];
__device__ float g_bmax[BB];
__device__ float g_bden[BB];
__device__ float g_part[BB][NCHUNK][DD];
__device__ __align__(16) __half g_Wqh[HH * DD];
__device__ __align__(16) __half g_Wkh[HH * DD];

// ---------------- helpers ----------------
static __device__ __forceinline__ uint32_t smem_u32(const void* p) {
    uint32_t a;
    asm("{ .reg .u64 t; cvta.to.shared.u64 t, %1; cvt.u32.u64 %0, t; }"
        : "=r"(a) : "l"(p));
    return a;
}

static __device__ __forceinline__ void ldsm_x4(uint32_t& r0, uint32_t& r1,
                                               uint32_t& r2, uint32_t& r3,
                                               uint32_t addr) {
    asm volatile("ldmatrix.sync.aligned.m8n8.x4.shared.b16 {%0,%1,%2,%3}, [%4];"
                 : "=r"(r0), "=r"(r1), "=r"(r2), "=r"(r3) : "r"(addr));
}

static __device__ __forceinline__ void mma_f16(float* c, const uint32_t* a,
                                               uint32_t b0, uint32_t b1) {
    asm volatile(
        "mma.sync.aligned.m16n8k16.row.col.f32.f16.f16.f32 "
        "{%0,%1,%2,%3}, {%4,%5,%6,%7}, {%8,%9}, {%0,%1,%2,%3};"
        : "+f"(c[0]), "+f"(c[1]), "+f"(c[2]), "+f"(c[3])
        : "r"(a[0]), "r"(a[1]), "r"(a[2]), "r"(a[3]), "r"(b0), "r"(b1));
}

static __device__ __forceinline__ void cp_async16(uint32_t saddr, const void* gptr) {
    asm volatile("cp.async.cg.shared.global [%0], [%1], 16;"
                 :: "r"(saddr), "l"(gptr) : "memory");
}
#define CP_COMMIT() asm volatile("cp.async.commit_group;" ::: "memory")
#define CP_WAIT0()  asm volatile("cp.async.wait_group 0;" ::: "memory")

static __device__ __forceinline__ uint32_t pack_h(__half a, __half b) {
    __half2 t(a, b);
    return *reinterpret_cast<uint32_t*>(&t);
}

// Accurate fp32 tanh (Eigen-style rational, ~few-ulp in [-7.9, 7.9]).
static __device__ __forceinline__ float tanh_fast(float x) {
    float xc = fminf(fmaxf(x, -7.90531110763549805f), 7.90531110763549805f);
    float x2 = xc * xc;
    float p = fmaf(x2, -2.76076847742355e-16f, 2.00018790482477e-13f);
    p = fmaf(p, x2, -8.60467152213735e-11f);
    p = fmaf(p, x2, 5.12229709037114e-08f);
    p = fmaf(p, x2, 1.48572235717979e-05f);
    p = fmaf(p, x2, 6.37261928875436e-04f);
    p = fmaf(p, x2, 4.89352455891786e-03f);
    float q = fmaf(x2, 1.19825839466702e-06f, 1.18534705686654e-04f);
    q = fmaf(q, x2, 2.26843463243900e-03f);
    q = fmaf(q, x2, 4.89352518554385e-03f);
    return __fdividef(xc * p, q);
}

// =====================================================================
// Setup: convert Wq/Wk fp32 -> fp16 in global scratch.
// =====================================================================
__global__ void wsplit_kernel(const float* __restrict__ Wq, const float* __restrict__ Wk) {
    const int i = blockIdx.x * 256 + threadIdx.x;
    g_Wqh[i] = __float2half_rn(Wq[i]);
    g_Wkh[i] = __float2half_rn(Wk[i]);
}

// =====================================================================
// Scores via HMMA, single fp16 pass. CTA tile: 32 rows x 256 h (full H).
// 8 warps, each owning a 32-col group (warp_n = wid), all sharing the
// 32 A-rows. 16 iterations: it<8 -> Q x Wq, it>=8 -> K x Wk.
// Double-buffered: STS A(cur); wait B(cur); sync; prefetch(next); MMA(cur).
// 3 CTAs/SM (46 KB smem, ~70 regs) -> 6 warps/SMSP for issue-slot coverage.
// =====================================================================
__global__ __launch_bounds__(256, 3)
void scores_mma_kernel(const float* __restrict__ Q, const float* __restrict__ K,
                       const float* __restrict__ Wv) {
    extern __shared__ __align__(128) char dyn[];
    __shared__ float s_wv[HH];
    __shared__ float s_red[8][TILE_M];

    const int tid = threadIdx.x;
    const int lane = tid & 31;
    const int warp_n = tid >> 5;     // 8 n-groups of 32 cols
    const int m0 = blockIdx.x * TILE_M;

    s_wv[tid] = Wv[tid];

    const uint32_t base = smem_u32(dyn);
#define SA_TILE(buf) (base + (buf) * BUF_BYTES)
#define SB_TILE(buf) (base + (buf) * BUF_BYTES + A_BYTES)

    // per-lane ldmatrix byte offsets (within a tile)
    uint32_t aoff[2][2];   // [mi][ks]
#pragma unroll
    for (int mi = 0; mi < 2; mi++)
#pragma unroll
        for (int ks = 0; ks < 2; ks++)
            aoff[mi][ks] = (uint32_t)((mi * 16 + (lane & 15)) * (SA * 2)
                                      + (ks * 16 + ((lane >> 4) * 8)) * 2);
    uint32_t boff[2][2];   // [ntp][ks]
#pragma unroll
    for (int ntp = 0; ntp < 2; ntp++)
#pragma unroll
        for (int ks = 0; ks < 2; ks++)
            boff[ntp][ks] = (uint32_t)((warp_n * 32 + ntp * 16 + (lane & 7) + ((lane >> 4) << 3)) * (SA * 2)
                                       + ks * 32 + ((lane >> 3) & 1) * 16);

    // A-staging geometry: 32 rows x 8 float4 = 256; 1 per thread
    const int ar = tid >> 3;         // row 0..31
    const int ac4 = tid & 7;
    // B cp.async geometry: 256 rows x 4 uint4 = 1024; 4 per thread
    const int br = tid >> 2;         // row 0..63 (j adds 64)
    const int bc8 = tid & 3;

    float c[2][4][4];
#pragma unroll
    for (int mi = 0; mi < 2; mi++)
#pragma unroll
        for (int nt = 0; nt < 4; nt++)
#pragma unroll
            for (int r = 0; r < 4; r++) c[mi][nt][r] = 0.f;

    uint32_t ah[2];   // staged converted A for "next" chunk (1 float4 -> 2 h2)

    // ---- prestage it=0 (src=Q, d0=0) ----
    {
        const float4 v = *reinterpret_cast<const float4*>(
            Q + (size_t)(m0 + ar) * DD + 0 + ac4 * 4);
        ah[0] = pack_h(__float2half_rn(v.x), __float2half_rn(v.y));
        ah[1] = pack_h(__float2half_rn(v.z), __float2half_rn(v.w));
#pragma unroll
        for (int j = 0; j < 4; j++) {
            const int r = br + 64 * j;
            const size_t goff = (size_t)r * DD + 0 + bc8 * 8;
            const uint32_t soff = (uint32_t)(r * SA + bc8 * 8) * 2;
            cp_async16(SB_TILE(0) + soff, g_Wqh + goff);
        }
        CP_COMMIT();
    }

#pragma unroll 1
    for (int it = 0; it < 16; it++) {
        const int buf = it & 1;

        // ---- STS staged A ----
        {
            const uint32_t soff = (uint32_t)(ar * SA + ac4 * 4) * 2;
            asm volatile("st.shared.v2.u32 [%0], {%1, %2};"
                         :: "r"(SA_TILE(buf) + soff), "r"(ah[0]), "r"(ah[1]));
        }
        CP_WAIT0();          // B(it) delivered
        __syncthreads();

        // ---- prefetch (it+1): LDG+convert A to regs, cp.async B ----
        if (it < 15) {
            const int nit = it + 1;
            const int nsrc = nit >> 3;
            const int nd0 = (nit & 7) * KC;
            const float* X = nsrc ? K : Q;
            const __half* WhG = nsrc ? g_Wkh : g_Wqh;
#pragma unroll
            for (int j = 0; j < 4; j++) {
                const int r = br + 64 * j;
                const size_t goff = (size_t)r * DD + nd0 + bc8 * 8;
                const uint32_t soff = (uint32_t)(r * SA + bc8 * 8) * 2;
                cp_async16(SB_TILE(buf ^ 1) + soff, WhG + goff);
            }
            CP_COMMIT();
            const float4 v = *reinterpret_cast<const float4*>(
                X + (size_t)(m0 + ar) * DD + nd0 + ac4 * 4);
            ah[0] = pack_h(__float2half_rn(v.x), __float2half_rn(v.y));
            ah[1] = pack_h(__float2half_rn(v.z), __float2half_rn(v.w));
        }

        // ---- MMA (single fp16 pass): 16 per warp per iter ----
#pragma unroll
        for (int ks = 0; ks < 2; ks++) {
            uint32_t a0[4], a1[4];
            ldsm_x4(a0[0], a0[1], a0[2], a0[3], SA_TILE(buf) + aoff[0][ks]);
            ldsm_x4(a1[0], a1[1], a1[2], a1[3], SA_TILE(buf) + aoff[1][ks]);
#pragma unroll
            for (int ntp = 0; ntp < 2; ntp++) {
                uint32_t b0, b1, b2, b3;
                ldsm_x4(b0, b1, b2, b3, SB_TILE(buf) + boff[ntp][ks]);
                mma_f16(c[0][ntp * 2 + 0], a0, b0, b1);
                mma_f16(c[0][ntp * 2 + 1], a0, b2, b3);
                mma_f16(c[1][ntp * 2 + 0], a1, b0, b1);
                mma_f16(c[1][ntp * 2 + 1], a1, b2, b3);
            }
        }
    }

    // ---- epilogue: tanh + Wv dot ----
    float sp[4] = {0.f, 0.f, 0.f, 0.f};
#pragma unroll
    for (int mi = 0; mi < 2; mi++)
#pragma unroll
        for (int nt = 0; nt < 4; nt++) {
            const int col = warp_n * 32 + nt * 8 + (lane & 3) * 2;
            const float w0 = s_wv[col], w1 = s_wv[col + 1];
            sp[mi * 2 + 0] = fmaf(w0, tanh_fast(c[mi][nt][0]),
                             fmaf(w1, tanh_fast(c[mi][nt][1]), sp[mi * 2 + 0]));
            sp[mi * 2 + 1] = fmaf(w0, tanh_fast(c[mi][nt][2]),
                             fmaf(w1, tanh_fast(c[mi][nt][3]), sp[mi * 2 + 1]));
        }

    // reduce 4 col-lanes -> row totals
#pragma unroll
    for (int i = 0; i < 4; i++) {
        sp[i] += __shfl_xor_sync(0xFFFFFFFFu, sp[i], 1);
        sp[i] += __shfl_xor_sync(0xFFFFFFFFu, sp[i], 2);
    }
    __syncthreads();
    if ((lane & 3) == 0) {
#pragma unroll
        for (int mi = 0; mi < 2; mi++)
#pragma unroll
            for (int half = 0; half < 2; half++) {
                const int row = mi * 16 + half * 8 + (lane >> 2);
                s_red[warp_n][row] = sp[mi * 2 + half];
            }
    }
    __syncthreads();
    if (tid < TILE_M) {
        float t = 0.f;
#pragma unroll
        for (int g = 0; g < 8; g++) t += s_red[g][tid];
        g_scores[m0 + tid] = t;
    }
#undef SA_TILE
#undef SB_TILE
}

// =====================================================================
// Kernel B: per-batch max / first-occurrence argmax / softmax denominator.
// =====================================================================
__global__ __launch_bounds__(1024)
void stats_kernel(float* __restrict__ out, int out_size) {
    const int b = blockIdx.x;
    const int tid = threadIdx.x;
    const float* s = g_scores + (long)b * NN;

    float m = -INFINITY;
    int mi = 0;
    for (int n = tid; n < NN; n += 1024) {
        const float v = s[n];
        if (v > m) { m = v; mi = n; }
    }
    __shared__ float sm[1024];
    __shared__ int   si[1024];
    sm[tid] = m; si[tid] = mi;
    __syncthreads();
    for (int o = 512; o > 0; o >>= 1) {
        if (tid < o) {
            const float v = sm[tid + o]; const int vi = si[tid + o];
            if (v > sm[tid] || (v == sm[tid] && vi < si[tid])) { sm[tid] = v; si[tid] = vi; }
        }
        __syncthreads();
    }
    const float mx = sm[0];
    const int amax = si[0];
    __syncthreads();

    float acc = 0.f;
    for (int n = tid; n < NN; n += 1024) acc += expf(s[n] - mx);
    sm[tid] = acc;
    __syncthreads();
    for (int o = 512; o > 0; o >>= 1) {
        if (tid < o) sm[tid] += sm[tid + o];
        __syncthreads();
    }
    if (tid == 0) {
        g_bmax[b] = mx;
        g_bden[b] = sm[0];
        if (out_size >= BB * DD + BB) out[BB * DD + b] = (float)amax;
    }
}

// =====================================================================
// Kernel C: partial weighted sums (deterministic, no atomics)
// chunk = 32 rows; grid (NCHUNK=128, BB) = 4096 blocks.
// =====================================================================
#define CROWS (NN / NCHUNK)   // 32
__global__ void weighted_kernel(const float* __restrict__ V) {
    const int chunk = blockIdx.x;
    const int b = blockIdx.y;
    const int tid = threadIdx.x;

    __shared__ float w[CROWS];
    __shared__ float part[4][DD];
    const float mx = g_bmax[b];
    const float inv = 1.0f / g_bden[b];
    const int n0 = chunk * CROWS;
    if (tid < CROWS)
        w[tid] = expf(g_scores[(long)b * NN + n0 + tid] - mx) * inv;
    __syncthreads();

    const int rg = tid >> 6;        // row-group 0..3
    const int c4 = tid & 63;        // float4 column
    const float4* Vp = reinterpret_cast<const float4*>(
        V + ((long)b * NN + n0) * DD) + c4;
    float4 acc = {0.f, 0.f, 0.f, 0.f};
#pragma unroll
    for (int n = rg; n < CROWS; n += 4) {
        const float4 v = Vp[(long)n * (DD / 4)];
        const float ww = w[n];
        acc.x = fmaf(ww, v.x, acc.x);
        acc.y = fmaf(ww, v.y, acc.y);
        acc.z = fmaf(ww, v.z, acc.z);
        acc.w = fmaf(ww, v.w, acc.w);
    }
    *reinterpret_cast<float4*>(&part[rg][c4 * 4]) = acc;
    __syncthreads();
    g_part[b][chunk][tid] = part[0][tid] + part[1][tid] + part[2][tid] + part[3][tid];
}

// =====================================================================
// Kernel D: reduce partials -> out[b, d]
// =====================================================================
__global__ void finalize_kernel(float* __restrict__ out) {
    const int b = blockIdx.x;
    const int tid = threadIdx.x;
    float acc = 0.f;
#pragma unroll 8
    for (int c = 0; c < NCHUNK; c++) acc += g_part[b][c][tid];
    out[b * DD + tid] = acc;
}

// =====================================================================
extern "C" void kernel_launch(void* const* d_in, const int* in_sizes, int n_in,
                              void* d_out, int out_size) {
    const float* Q  = (const float*)d_in[0];
    const float* K  = (const float*)d_in[1];
    const float* V  = (const float*)d_in[2];
    const float* Wq = (const float*)d_in[3];
    const float* Wk = (const float*)d_in[4];
    const float* Wv = (const float*)d_in[5];
    float* out = (float*)d_out;

    cudaFuncSetAttribute(scores_mma_kernel,
                         cudaFuncAttributeMaxDynamicSharedMemorySize, DYN_SMEM);

    wsplit_kernel<<<HH * DD / 256, 256>>>(Wq, Wk);
    scores_mma_kernel<<<NTILES, 256, DYN_SMEM>>>(Q, K, Wv);
    stats_kernel<<<BB, 1024>>>(out, out_size);
    weighted_kernel<<<dim3(NCHUNK, BB), 256>>>(V);
    finalize_kernel<<<BB, DD>>>(out);
}

// round 11
// speedup vs baseline: 1.4282x; 1.4282x over previous
#include <cuda_runtime.h>
#include <cuda_fp16.h>
#include <cstdint>
#include <math.h>

// Shapes fixed by the reference: B=32, N=4096, D=256, H=256
#define BB 32
#define NN 4096
#define DD 256
#define HH 256
#define MTOT (BB * NN)          // 131072 rows
#define TILE_M 64               // rows per CTA
#define NTILES (MTOT / TILE_M)  // 2048
#define NCHUNK 128
#define KC 64                   // d-chunk (halves iteration count vs KC=32)
#define SA 72                   // padded smem row stride in fp16 elems (144 B)
#define A_BYTES (TILE_M * SA * 2)     // 9216
#define B_BYTES (HH * SA * 2)         // 36864
#define BUF_BYTES (A_BYTES + B_BYTES) // 46080
#define DYN_SMEM (2 * BUF_BYTES)      // 92160

// ---------------- device scratch (no allocation allowed) ----------------
__device__ float g_scores[MTOT];
__device__ float g_bmax[BB];
__device__ float g_bden[BB];
__device__ float g_part[BB][NCHUNK][DD];
__device__ __align__(16) __half g_Wqh[HH * DD];
__device__ __align__(16) __half g_Wkh[HH * DD];

// ---------------- helpers ----------------
static __device__ __forceinline__ uint32_t smem_u32(const void* p) {
    uint32_t a;
    asm("{ .reg .u64 t; cvta.to.shared.u64 t, %1; cvt.u32.u64 %0, t; }"
        : "=r"(a) : "l"(p));
    return a;
}

static __device__ __forceinline__ void ldsm_x4(uint32_t& r0, uint32_t& r1,
                                               uint32_t& r2, uint32_t& r3,
                                               uint32_t addr) {
    asm volatile("ldmatrix.sync.aligned.m8n8.x4.shared.b16 {%0,%1,%2,%3}, [%4];"
                 : "=r"(r0), "=r"(r1), "=r"(r2), "=r"(r3) : "r"(addr));
}

static __device__ __forceinline__ void mma_f16(float* c, const uint32_t* a,
                                               uint32_t b0, uint32_t b1) {
    asm volatile(
        "mma.sync.aligned.m16n8k16.row.col.f32.f16.f16.f32 "
        "{%0,%1,%2,%3}, {%4,%5,%6,%7}, {%8,%9}, {%0,%1,%2,%3};"
        : "+f"(c[0]), "+f"(c[1]), "+f"(c[2]), "+f"(c[3])
        : "r"(a[0]), "r"(a[1]), "r"(a[2]), "r"(a[3]), "r"(b0), "r"(b1));
}

static __device__ __forceinline__ void cp_async16(uint32_t saddr, const void* gptr) {
    asm volatile("cp.async.cg.shared.global [%0], [%1], 16;"
                 :: "r"(saddr), "l"(gptr) : "memory");
}
#define CP_COMMIT() asm volatile("cp.async.commit_group;" ::: "memory")
#define CP_WAIT0()  asm volatile("cp.async.wait_group 0;" ::: "memory")

static __device__ __forceinline__ uint32_t pack_h(__half a, __half b) {
    __half2 t(a, b);
    return *reinterpret_cast<uint32_t*>(&t);
}

// Accurate fp32 tanh (Eigen-style rational, ~few-ulp in [-7.9, 7.9]).
static __device__ __forceinline__ float tanh_fast(float x) {
    float xc = fminf(fmaxf(x, -7.90531110763549805f), 7.90531110763549805f);
    float x2 = xc * xc;
    float p = fmaf(x2, -2.76076847742355e-16f, 2.00018790482477e-13f);
    p = fmaf(p, x2, -8.60467152213735e-11f);
    p = fmaf(p, x2, 5.12229709037114e-08f);
    p = fmaf(p, x2, 1.48572235717979e-05f);
    p = fmaf(p, x2, 6.37261928875436e-04f);
    p = fmaf(p, x2, 4.89352455891786e-03f);
    float q = fmaf(x2, 1.19825839466702e-06f, 1.18534705686654e-04f);
    q = fmaf(q, x2, 2.26843463243900e-03f);
    q = fmaf(q, x2, 4.89352518554385e-03f);
    return __fdividef(xc * p, q);
}

// =====================================================================
// Setup: convert Wq/Wk fp32 -> fp16 in global scratch.
// =====================================================================
__global__ void wsplit_kernel(const float* __restrict__ Wq, const float* __restrict__ Wk) {
    const int i = blockIdx.x * 256 + threadIdx.x;
    g_Wqh[i] = __float2half_rn(Wq[i]);
    g_Wkh[i] = __float2half_rn(Wk[i]);
}

// =====================================================================
// Scores via HMMA, single fp16 pass. CTA tile: 64 rows x 256 h (full H).
// 8 warps: warp_m in {0,1}, warp_n in {0..3}. KC=64 d-chunks -> only 8
// pipeline iterations (it<4: Q x Wq, it>=4: K x Wk), 32 MMA/warp/iter.
// Double-buffered: STS A(cur); wait B(cur); sync; prefetch(next); MMA(cur).
// =====================================================================
__global__ __launch_bounds__(256, 2)
void scores_mma_kernel(const float* __restrict__ Q, const float* __restrict__ K,
                       const float* __restrict__ Wv) {
    extern __shared__ __align__(128) char dyn[];
    __shared__ float s_wv[HH];
    __shared__ float s_red[4][TILE_M];

    const int tid = threadIdx.x;
    const int lane = tid & 31;
    const int wid = tid >> 5;
    const int warp_m = wid & 1;      // 2 m-groups of 32 rows
    const int warp_n = wid >> 1;     // 4 n-groups of 64 cols
    const int m0 = blockIdx.x * TILE_M;

    s_wv[tid] = Wv[tid];

    const uint32_t base = smem_u32(dyn);
#define SA_TILE(buf) (base + (buf) * BUF_BYTES)
#define SB_TILE(buf) (base + (buf) * BUF_BYTES + A_BYTES)

    // per-lane ldmatrix byte offsets (within a tile); ks = 16-elem k-step (0..3)
    uint32_t aoff[2][4];   // [mi][ks]
#pragma unroll
    for (int mi = 0; mi < 2; mi++)
#pragma unroll
        for (int ks = 0; ks < 4; ks++)
            aoff[mi][ks] = (uint32_t)((warp_m * 32 + mi * 16 + (lane & 15)) * (SA * 2)
                                      + (ks * 16 + ((lane >> 4) * 8)) * 2);
    uint32_t boff[4][4];   // [ntp][ks]
#pragma unroll
    for (int ntp = 0; ntp < 4; ntp++)
#pragma unroll
        for (int ks = 0; ks < 4; ks++)
            boff[ntp][ks] = (uint32_t)((warp_n * 64 + ntp * 16 + (lane & 7) + ((lane >> 4) << 3)) * (SA * 2)
                                       + ks * 32 + ((lane >> 3) & 1) * 16);

    // A-staging geometry: 64 rows x 16 float4 = 1024; 4 per thread
    // idx = tid + 256*j -> r = idx>>4, c4 = idx&15
    // B cp.async geometry: 256 rows x 8 uint4 = 2048; 8 per thread
    // idx = tid + 256*j -> r = idx>>3, c8 = idx&7

    float c[2][8][4];
#pragma unroll
    for (int mi = 0; mi < 2; mi++)
#pragma unroll
        for (int nt = 0; nt < 8; nt++)
#pragma unroll
            for (int r = 0; r < 4; r++) c[mi][nt][r] = 0.f;

    uint32_t ah[8];   // staged converted A (4 float4 -> 8 h2)

    // ---- prestage it=0 (src=Q, d0=0) ----
    {
#pragma unroll
        for (int j = 0; j < 4; j++) {
            const int idx = tid + 256 * j;
            const int r = idx >> 4, c4 = idx & 15;
            const float4 v = *reinterpret_cast<const float4*>(
                Q + (size_t)(m0 + r) * DD + 0 + c4 * 4);
            ah[2*j]   = pack_h(__float2half_rn(v.x), __float2half_rn(v.y));
            ah[2*j+1] = pack_h(__float2half_rn(v.z), __float2half_rn(v.w));
        }
#pragma unroll
        for (int j = 0; j < 8; j++) {
            const int idx = tid + 256 * j;
            const int r = idx >> 3, c8 = idx & 7;
            const size_t goff = (size_t)r * DD + 0 + c8 * 8;
            const uint32_t soff = (uint32_t)(r * SA + c8 * 8) * 2;
            cp_async16(SB_TILE(0) + soff, g_Wqh + goff);
        }
        CP_COMMIT();
    }

#pragma unroll 1
    for (int it = 0; it < 8; it++) {
        const int buf = it & 1;

        // ---- STS staged A ----
#pragma unroll
        for (int j = 0; j < 4; j++) {
            const int idx = tid + 256 * j;
            const int r = idx >> 4, c4 = idx & 15;
            const uint32_t soff = (uint32_t)(r * SA + c4 * 4) * 2;
            asm volatile("st.shared.v2.u32 [%0], {%1, %2};"
                         :: "r"(SA_TILE(buf) + soff), "r"(ah[2*j]), "r"(ah[2*j+1]));
        }
        CP_WAIT0();          // B(it) delivered
        __syncthreads();

        // ---- prefetch (it+1): LDG+convert A to regs, cp.async B ----
        if (it < 7) {
            const int nit = it + 1;
            const int nsrc = nit >> 2;
            const int nd0 = (nit & 3) * KC;
            const float* X = nsrc ? K : Q;
            const __half* WhG = nsrc ? g_Wkh : g_Wqh;
#pragma unroll
            for (int j = 0; j < 8; j++) {
                const int idx = tid + 256 * j;
                const int r = idx >> 3, c8 = idx & 7;
                const size_t goff = (size_t)r * DD + nd0 + c8 * 8;
                const uint32_t soff = (uint32_t)(r * SA + c8 * 8) * 2;
                cp_async16(SB_TILE(buf ^ 1) + soff, WhG + goff);
            }
            CP_COMMIT();
#pragma unroll
            for (int j = 0; j < 4; j++) {
                const int idx = tid + 256 * j;
                const int r = idx >> 4, c4 = idx & 15;
                const float4 v = *reinterpret_cast<const float4*>(
                    X + (size_t)(m0 + r) * DD + nd0 + c4 * 4);
                ah[2*j]   = pack_h(__float2half_rn(v.x), __float2half_rn(v.y));
                ah[2*j+1] = pack_h(__float2half_rn(v.z), __float2half_rn(v.w));
            }
        }

        // ---- MMA (single fp16 pass): 4 k-steps x 8 n-tiles ----
#pragma unroll
        for (int ks = 0; ks < 4; ks++) {
            uint32_t a0[4], a1[4];
            ldsm_x4(a0[0], a0[1], a0[2], a0[3], SA_TILE(buf) + aoff[0][ks]);
            ldsm_x4(a1[0], a1[1], a1[2], a1[3], SA_TILE(buf) + aoff[1][ks]);
#pragma unroll
            for (int ntp = 0; ntp < 4; ntp++) {
                uint32_t b0, b1, b2, b3;
                ldsm_x4(b0, b1, b2, b3, SB_TILE(buf) + boff[ntp][ks]);
                mma_f16(c[0][ntp * 2 + 0], a0, b0, b1);
                mma_f16(c[0][ntp * 2 + 1], a0, b2, b3);
                mma_f16(c[1][ntp * 2 + 0], a1, b0, b1);
                mma_f16(c[1][ntp * 2 + 1], a1, b2, b3);
            }
        }
    }

    // ---- epilogue: tanh + Wv dot ----
    float sp[4] = {0.f, 0.f, 0.f, 0.f};
#pragma unroll
    for (int mi = 0; mi < 2; mi++)
#pragma unroll
        for (int nt = 0; nt < 8; nt++) {
            const int col = warp_n * 64 + nt * 8 + (lane & 3) * 2;
            const float w0 = s_wv[col], w1 = s_wv[col + 1];
            sp[mi * 2 + 0] = fmaf(w0, tanh_fast(c[mi][nt][0]),
                             fmaf(w1, tanh_fast(c[mi][nt][1]), sp[mi * 2 + 0]));
            sp[mi * 2 + 1] = fmaf(w0, tanh_fast(c[mi][nt][2]),
                             fmaf(w1, tanh_fast(c[mi][nt][3]), sp[mi * 2 + 1]));
        }

    // reduce 4 col-lanes -> row totals
#pragma unroll
    for (int i = 0; i < 4; i++) {
        sp[i] += __shfl_xor_sync(0xFFFFFFFFu, sp[i], 1);
        sp[i] += __shfl_xor_sync(0xFFFFFFFFu, sp[i], 2);
    }
    __syncthreads();
    if ((lane & 3) == 0) {
#pragma unroll
        for (int mi = 0; mi < 2; mi++)
#pragma unroll
            for (int half = 0; half < 2; half++) {
                const int row = warp_m * 32 + mi * 16 + half * 8 + (lane >> 2);
                s_red[warp_n][row] = sp[mi * 2 + half];
            }
    }
    __syncthreads();
    if (tid < TILE_M)
        g_scores[m0 + tid] = (s_red[0][tid] + s_red[1][tid])
                           + (s_red[2][tid] + s_red[3][tid]);
#undef SA_TILE
#undef SB_TILE
}

// =====================================================================
// Kernel B: per-batch max / first-occurrence argmax / softmax denominator.
// =====================================================================
__global__ __launch_bounds__(1024)
void stats_kernel(float* __restrict__ out, int out_size) {
    const int b = blockIdx.x;
    const int tid = threadIdx.x;
    const float* s = g_scores + (long)b * NN;

    float m = -INFINITY;
    int mi = 0;
    for (int n = tid; n < NN; n += 1024) {
        const float v = s[n];
        if (v > m) { m = v; mi = n; }
    }
    __shared__ float sm[1024];
    __shared__ int   si[1024];
    sm[tid] = m; si[tid] = mi;
    __syncthreads();
    for (int o = 512; o > 0; o >>= 1) {
        if (tid < o) {
            const float v = sm[tid + o]; const int vi = si[tid + o];
            if (v > sm[tid] || (v == sm[tid] && vi < si[tid])) { sm[tid] = v; si[tid] = vi; }
        }
        __syncthreads();
    }
    const float mx = sm[0];
    const int amax = si[0];
    __syncthreads();

    float acc = 0.f;
    for (int n = tid; n < NN; n += 1024) acc += expf(s[n] - mx);
    sm[tid] = acc;
    __syncthreads();
    for (int o = 512; o > 0; o >>= 1) {
        if (tid < o) sm[tid] += sm[tid + o];
        __syncthreads();
    }
    if (tid == 0) {
        g_bmax[b] = mx;
        g_bden[b] = sm[0];
        if (out_size >= BB * DD + BB) out[BB * DD + b] = (float)amax;
    }
}

// =====================================================================
// Kernel C: partial weighted sums (deterministic, no atomics)
// chunk = 32 rows; grid (NCHUNK=128, BB) = 4096 blocks.
// =====================================================================
#define CROWS (NN / NCHUNK)   // 32
__global__ void weighted_kernel(const float* __restrict__ V) {
    const int chunk = blockIdx.x;
    const int b = blockIdx.y;
    const int tid = threadIdx.x;

    __shared__ float w[CROWS];
    __shared__ float part[4][DD];
    const float mx = g_bmax[b];
    const float inv = 1.0f / g_bden[b];
    const int n0 = chunk * CROWS;
    if (tid < CROWS)
        w[tid] = expf(g_scores[(long)b * NN + n0 + tid] - mx) * inv;
    __syncthreads();

    const int rg = tid >> 6;        // row-group 0..3
    const int c4 = tid & 63;        // float4 column
    const float4* Vp = reinterpret_cast<const float4*>(
        V + ((long)b * NN + n0) * DD) + c4;
    float4 acc = {0.f, 0.f, 0.f, 0.f};
#pragma unroll
    for (int n = rg; n < CROWS; n += 4) {
        const float4 v = Vp[(long)n * (DD / 4)];
        const float ww = w[n];
        acc.x = fmaf(ww, v.x, acc.x);
        acc.y = fmaf(ww, v.y, acc.y);
        acc.z = fmaf(ww, v.z, acc.z);
        acc.w = fmaf(ww, v.w, acc.w);
    }
    *reinterpret_cast<float4*>(&part[rg][c4 * 4]) = acc;
    __syncthreads();
    g_part[b][chunk][tid] = part[0][tid] + part[1][tid] + part[2][tid] + part[3][tid];
}

// =====================================================================
// Kernel D: reduce partials -> out[b, d]
// =====================================================================
__global__ void finalize_kernel(float* __restrict__ out) {
    const int b = blockIdx.x;
    const int tid = threadIdx.x;
    float acc = 0.f;
#pragma unroll 8
    for (int c = 0; c < NCHUNK; c++) acc += g_part[b][c][tid];
    out[b * DD + tid] = acc;
}

// =====================================================================
extern "C" void kernel_launch(void* const* d_in, const int* in_sizes, int n_in,
                              void* d_out, int out_size) {
    const float* Q  = (const float*)d_in[0];
    const float* K  = (const float*)d_in[1];
    const float* V  = (const float*)d_in[2];
    const float* Wq = (const float*)d_in[3];
    const float* Wk = (const float*)d_in[4];
    const float* Wv = (const float*)d_in[5];
    float* out = (float*)d_out;

    cudaFuncSetAttribute(scores_mma_kernel,
                         cudaFuncAttributeMaxDynamicSharedMemorySize, DYN_SMEM);

    wsplit_kernel<<<HH * DD / 256, 256>>>(Wq, Wk);
    scores_mma_kernel<<<NTILES, 256, DYN_SMEM>>>(Q, K, Wv);
    stats_kernel<<<BB, 1024>>>(out, out_size);
    weighted_kernel<<<dim3(NCHUNK, BB), 256>>>(V);
    finalize_kernel<<<BB, DD>>>(out);
}